// round 15
// baseline (speedup 1.0000x reference)
#include <cuda_runtime.h>
#include <cuda_fp16.h>
#include <math.h>

#define NN   50000
#define EE   1600000
#define IND  256
#define HD   64
#define CD   16
#define NTR  5000
#define NH   (NN*HD)
#define SCB  ((NN + 255) / 256)   // 196 scan blocks
#define NPB  ((NN + 255) / 256)   // normpred blocks

// Scratch (no allocs allowed)
__device__ __align__(16) __half   g_t[NH];     // x @ W  (fp16 message buffer)
__device__ __align__(16) float    g_h[NH];     // layer output (fp32)
__device__ __align__(16) unsigned g_e[EE];     // {u16 src | fp16 norm}, bucketed by dst
__device__ float g_dinv[NN];
__device__ int   g_deg[NN];                    // zero-init; self-restored by k_scan
__device__ int   g_off[NN];                    // bucket begin
__device__ int   g_end[NN];                    // bucket end
__device__ int   g_cur[NN];                    // fill cursors
__device__ unsigned g_pos;                     // zero-init; self-restored by k_scan
__device__ unsigned g_ctr;                     // zero-init; wraps (normpred)
__device__ unsigned g_ctr2;                    // zero-init; wraps (scan)

// ---------------------------------------------------------------------------
__device__ __forceinline__ unsigned long long fma2(unsigned long long a,
                                                   unsigned long long b,
                                                   unsigned long long c) {
    unsigned long long d;
    asm("fma.rn.f32x2 %0, %1, %2, %3;" : "=l"(d) : "l"(a), "l"(b), "l"(c));
    return d;
}
union U64F2 { unsigned long long u; float2 f; };
__device__ __forceinline__ float2 asf2(unsigned long long u) {
    U64F2 t; t.u = u; return t.f;
}
__device__ __forceinline__ float enorm(unsigned e) {
    return __half2float(__ushort_as_half((unsigned short)(e >> 16)));
}

// ---------------------------------------------------------------------------
// Degree histogram; int4-vectorized edge reads (EE % 1024 == 0 → exact).
__global__ void k_deg(const int* __restrict__ dst) {
    int i = blockIdx.x * blockDim.x + threadIdx.x;
    if (i * 4 >= EE) return;
    int4 d4 = __ldg((const int4*)dst + i);
    atomicAdd(&g_deg[d4.x], 1);
    atomicAdd(&g_deg[d4.y], 1);
    atomicAdd(&g_deg[d4.z], 1);
    atomicAdd(&g_deg[d4.w], 1);
}

// Single-kernel CSR offsets: block scan + atomic base. Bucket order arbitrary.
__global__ void k_scan() {
    __shared__ int ss[256];
    __shared__ int sbase;
    __shared__ int s_last;
    int t = threadIdx.x;
    int idx = blockIdx.x * 256 + t;
    int d = 0;
    if (idx < NN) {
        d = g_deg[idx];
        g_deg[idx] = 0;                        // restore for next call
        g_dinv[idx] = rsqrtf((float)d + 1.0f); // +1 self-loop
    }
    ss[t] = d;
    __syncthreads();
#pragma unroll
    for (int o = 1; o < 256; o <<= 1) {
        int v = (t >= o) ? ss[t - o] : 0;
        __syncthreads();
        ss[t] += v;
        __syncthreads();
    }
    int inc = ss[t];
    if (t == 255) sbase = (int)atomicAdd(&g_pos, (unsigned)inc);
    __syncthreads();
    if (idx < NN) {
        int beg = sbase + inc - d;
        g_off[idx] = beg;
        g_cur[idx] = beg;
        g_end[idx] = beg + d;
    }
    __threadfence();
    __syncthreads();
    if (t == 0) {
        unsigned tk = atomicInc(&g_ctr2, SCB - 1);
        s_last = (tk == SCB - 1);
    }
    __syncthreads();
    if (s_last && t == 0) g_pos = 0;
}

// Bucket edges by dst; one 4B packed store per edge.
__global__ void k_fill(const int* __restrict__ src, const int* __restrict__ dst) {
    int e = blockIdx.x * blockDim.x + threadIdx.x;
    if (e >= EE) return;
    int s = src[e], d = dst[e];
    int pos = atomicAdd(&g_cur[d], 1);
    float nm = g_dinv[s] * g_dinv[d];
    g_e[pos] = (unsigned)s |
               ((unsigned)__half_as_ushort(__float2half_rn(nm)) << 16);
}

// ---------------------------------------------------------------------------
// O[N,64] = A[N,K] @ W[K,64], fp32 compute, fp16 output.
template <int K>
__global__ void __launch_bounds__(256) k_gemm(const float* __restrict__ A,
                                              const float* __restrict__ W,
                                              __half* __restrict__ O) {
    __shared__ __align__(16) float sAT[32][132];
    __shared__ __align__(16) float sWd[32][136];
    const int tid = threadIdx.x;
    const int rg = tid & 15;
    const int cg = tid >> 4;
    const int rb = blockIdx.x * 128;

    unsigned long long acc[4][4];
#pragma unroll
    for (int i = 0; i < 4; i++)
#pragma unroll
        for (int j = 0; j < 4; j++) acc[i][j] = 0ull;

    for (int kc = 0; kc < K; kc += 32) {
#pragma unroll
        for (int it = 0; it < 4; it++) {
            int i = tid + it * 256;
            int r = i >> 3, k4 = i & 7;
            int row = rb + r;
            float4 v = (row < NN)
                ? *(const float4*)(A + (size_t)row * K + kc + k4 * 4)
                : make_float4(0.f, 0.f, 0.f, 0.f);
            sAT[k4 * 4 + 0][r] = v.x;
            sAT[k4 * 4 + 1][r] = v.y;
            sAT[k4 * 4 + 2][r] = v.z;
            sAT[k4 * 4 + 3][r] = v.w;
        }
#pragma unroll
        for (int it = 0; it < 2; it++) {
            int i = tid + it * 256;
            int c4 = i & 15, k = i >> 4;
            float4 v = *(const float4*)(W + (size_t)(kc + k) * HD + c4 * 4);
            float2* wp = (float2*)&sWd[k][c4 * 8];
            wp[0] = make_float2(v.x, v.x);
            wp[1] = make_float2(v.y, v.y);
            wp[2] = make_float2(v.z, v.z);
            wp[3] = make_float2(v.w, v.w);
        }
        __syncthreads();
#pragma unroll 8
        for (int k = 0; k < 32; k++) {
            ulonglong2 a01 = *(const ulonglong2*)&sAT[k][rg * 8];
            ulonglong2 a23 = *(const ulonglong2*)&sAT[k][rg * 8 + 4];
            ulonglong2 w01 = *(const ulonglong2*)&sWd[k][cg * 8];
            ulonglong2 w23 = *(const ulonglong2*)&sWd[k][cg * 8 + 4];
            acc[0][0] = fma2(a01.x, w01.x, acc[0][0]);
            acc[0][1] = fma2(a01.x, w01.y, acc[0][1]);
            acc[0][2] = fma2(a01.x, w23.x, acc[0][2]);
            acc[0][3] = fma2(a01.x, w23.y, acc[0][3]);
            acc[1][0] = fma2(a01.y, w01.x, acc[1][0]);
            acc[1][1] = fma2(a01.y, w01.y, acc[1][1]);
            acc[1][2] = fma2(a01.y, w23.x, acc[1][2]);
            acc[1][3] = fma2(a01.y, w23.y, acc[1][3]);
            acc[2][0] = fma2(a23.x, w01.x, acc[2][0]);
            acc[2][1] = fma2(a23.x, w01.y, acc[2][1]);
            acc[2][2] = fma2(a23.x, w23.x, acc[2][2]);
            acc[2][3] = fma2(a23.x, w23.y, acc[2][3]);
            acc[3][0] = fma2(a23.y, w01.x, acc[3][0]);
            acc[3][1] = fma2(a23.y, w01.y, acc[3][1]);
            acc[3][2] = fma2(a23.y, w23.x, acc[3][2]);
            acc[3][3] = fma2(a23.y, w23.y, acc[3][3]);
        }
        __syncthreads();
    }
#pragma unroll
    for (int rp = 0; rp < 4; rp++) {
        float2 c0 = asf2(acc[rp][0]);
        float2 c1 = asf2(acc[rp][1]);
        float2 c2 = asf2(acc[rp][2]);
        float2 c3 = asf2(acc[rp][3]);
        int row0 = rb + rg * 8 + rp * 2;
        if (row0 < NN) {
            union { uint2 u; __half2 h[2]; } pk;
            pk.h[0] = __floats2half2_rn(c0.x, c1.x);
            pk.h[1] = __floats2half2_rn(c2.x, c3.x);
            *(uint2*)(O + (size_t)row0 * HD + cg * 4) = pk.u;
        }
        if (row0 + 1 < NN) {
            union { uint2 u; __half2 h[2]; } pk;
            pk.h[0] = __floats2half2_rn(c0.y, c1.y);
            pk.h[1] = __floats2half2_rn(c2.y, c3.y);
            *(uint2*)(O + (size_t)(row0 + 1) * HD + cg * 4) = pk.u;
        }
    }
}

// ---------------------------------------------------------------------------
// Warp-per-node CSR gather: lane owns halves {2*lane, 2*lane+1} (one uint/row).
// Edge words broadcast-loaded 4 at a time; no intra-warp divergence.
__global__ void __launch_bounds__(256) k_gather(const __half* __restrict__ t,
                                                float* __restrict__ h,
                                                const float* __restrict__ b,
                                                int relu) {
    int node = (blockIdx.x * blockDim.x + threadIdx.x) >> 5;
    int lane = threadIdx.x & 31;
    if (node >= NN) return;
    const unsigned* tv = (const unsigned*)t;   // 32 uints per 64-half row

    float di = g_dinv[node];
    float di2 = di * di;
    float2 s = __half22float2(*(__half2*)&tv[(size_t)node * 32 + lane]);
    float ax = s.x * di2, ay = s.y * di2;
    float bx = 0.f, by = 0.f;
    float cx = 0.f, cy = 0.f;
    float dx = 0.f, dy = 0.f;

    int i = g_off[node], end = g_end[node];
    // prologue: align i to 4 for uint4 broadcast edge loads
    while ((i & 3) && i < end) {
        unsigned e = __ldg(&g_e[i]);
        unsigned rw = __ldg(&tv[(size_t)(e & 0xFFFFu) * 32 + lane]);
        float2 f = __half22float2(*(__half2*)&rw);
        float nm = enorm(e);
        ax += nm * f.x; ay += nm * f.y;
        i++;
    }
    for (; i + 4 <= end; i += 4) {
        uint4 e4 = __ldg((const uint4*)&g_e[i]);   // same addr all lanes → bcast
        unsigned r0 = __ldg(&tv[(size_t)(e4.x & 0xFFFFu) * 32 + lane]);
        unsigned r1 = __ldg(&tv[(size_t)(e4.y & 0xFFFFu) * 32 + lane]);
        unsigned r2 = __ldg(&tv[(size_t)(e4.z & 0xFFFFu) * 32 + lane]);
        unsigned r3 = __ldg(&tv[(size_t)(e4.w & 0xFFFFu) * 32 + lane]);
        float n0 = enorm(e4.x), n1 = enorm(e4.y);
        float n2 = enorm(e4.z), n3 = enorm(e4.w);
        float2 f0 = __half22float2(*(__half2*)&r0);
        float2 f1 = __half22float2(*(__half2*)&r1);
        float2 f2 = __half22float2(*(__half2*)&r2);
        float2 f3 = __half22float2(*(__half2*)&r3);
        ax += n0 * f0.x; ay += n0 * f0.y;
        bx += n1 * f1.x; by += n1 * f1.y;
        cx += n2 * f2.x; cy += n2 * f2.y;
        dx += n3 * f3.x; dy += n3 * f3.y;
    }
    for (; i < end; i++) {
        unsigned e = __ldg(&g_e[i]);
        unsigned rw = __ldg(&tv[(size_t)(e & 0xFFFFu) * 32 + lane]);
        float2 f = __half22float2(*(__half2*)&rw);
        float nm = enorm(e);
        ax += nm * f.x; ay += nm * f.y;
    }
    ax += bx + cx + dx;
    ay += by + cy + dy;

    float2 bb = __ldg((const float2*)b + lane);
    ax += bb.x; ay += bb.y;
    if (relu) { ax = fmaxf(ax, 0.f); ay = fmaxf(ay, 0.f); }
    ((float2*)(h + (size_t)node * HD))[lane] = make_float2(ax, ay);
}

// ---------------------------------------------------------------------------
// Fused: L2-normalize -> out_h, logits -> log_softmax -> out_pred, last-block NLL.
__global__ void k_normpred(const float* __restrict__ h, float* __restrict__ out_h,
                           const float* __restrict__ W3, const float* __restrict__ b3,
                           float* __restrict__ pred,
                           const int* __restrict__ labels, const int* __restrict__ tidx,
                           float* __restrict__ out) {
    __shared__ float sW[HD * CD];
    __shared__ float sb[CD];
    __shared__ int s_last;
    for (int i = threadIdx.x; i < HD * CD; i += blockDim.x) sW[i] = W3[i];
    if (threadIdx.x < CD) sb[threadIdx.x] = b3[threadIdx.x];
    __syncthreads();
    int n = blockIdx.x * blockDim.x + threadIdx.x;

    if (n < NN) {
        const float4* hv = (const float4*)(h + (size_t)n * HD);
        float4 r[16];
        float ss = 0.f;
#pragma unroll
        for (int i = 0; i < 16; i++) {
            float4 v = hv[i];
            r[i] = v;
            ss += v.x * v.x + v.y * v.y + v.z * v.z + v.w * v.w;
        }
        float sc = 1.0f / fmaxf(sqrtf(ss), 1e-12f);

        float z[CD];
#pragma unroll
        for (int c = 0; c < CD; c++) z[c] = sb[c];
        float* oo = out_h + (size_t)n * HD;
#pragma unroll
        for (int k4 = 0; k4 < 16; k4++) {
            float4 v = r[k4];
            v.x *= sc; v.y *= sc; v.z *= sc; v.w *= sc;
            oo[k4 * 4 + 0] = v.x;
            oo[k4 * 4 + 1] = v.y;
            oo[k4 * 4 + 2] = v.z;
            oo[k4 * 4 + 3] = v.w;
            const float* w0 = &sW[(k4 * 4 + 0) * CD];
            const float* w1 = &sW[(k4 * 4 + 1) * CD];
            const float* w2 = &sW[(k4 * 4 + 2) * CD];
            const float* w3 = &sW[(k4 * 4 + 3) * CD];
#pragma unroll
            for (int c = 0; c < CD; c++)
                z[c] += v.x * w0[c] + v.y * w1[c] + v.z * w2[c] + v.w * w3[c];
        }
        float m = z[0];
#pragma unroll
        for (int c = 1; c < CD; c++) m = fmaxf(m, z[c]);
        float se = 0.f;
#pragma unroll
        for (int c = 0; c < CD; c++) se += expf(z[c] - m);
        float lse = m + logf(se);
        float* po = pred + (size_t)n * CD;
#pragma unroll
        for (int c = 0; c < CD; c++) po[c] = z[c] - lse;
    }

    __threadfence();
    __syncthreads();
    if (threadIdx.x == 0) {
        unsigned tk = atomicInc(&g_ctr, NPB - 1);
        s_last = (tk == NPB - 1);
    }
    __syncthreads();
    if (s_last) {
        __shared__ float sred[256];
        float s = 0.f;
        for (int i = threadIdx.x; i < NTR; i += 256) {
            int idx = tidx[i];
            s += pred[(size_t)idx * CD + labels[idx]];
        }
        sred[threadIdx.x] = s;
        __syncthreads();
        for (int o = 128; o > 0; o >>= 1) {
            if (threadIdx.x < o) sred[threadIdx.x] += sred[threadIdx.x + o];
            __syncthreads();
        }
        if (threadIdx.x == 0) out[0] = -sred[0] / (float)NTR;
    }
}

// ---------------------------------------------------------------------------
extern "C" void kernel_launch(void* const* d_in, const int* in_sizes, int n_in,
                              void* d_out, int out_size) {
    const float* feats  = (const float*)d_in[0];
    const float* W1     = (const float*)d_in[1];
    const float* b1     = (const float*)d_in[2];
    const float* W2     = (const float*)d_in[3];
    const float* b2     = (const float*)d_in[4];
    const float* W3     = (const float*)d_in[5];
    const float* b3     = (const float*)d_in[6];
    const int*   edges  = (const int*)d_in[7];
    const int*   labels = (const int*)d_in[8];
    const int*   tidx   = (const int*)d_in[9];

    float* out      = (float*)d_out;
    float* out_pred = out + 1;
    float* out_h    = out + 1 + (size_t)NN * CD;

    __half* t_ptr; cudaGetSymbolAddress((void**)&t_ptr, g_t);
    float*  h_ptr; cudaGetSymbolAddress((void**)&h_ptr, g_h);

    const int* src = edges;        // edge_list[0]
    const int* dst = edges + EE;   // edge_list[1]

    static cudaStream_t s2 = 0;
    static cudaEvent_t evFork = 0, evJoin = 0;
    if (s2 == 0) {
        cudaStreamCreate(&s2);
        cudaEventCreateWithFlags(&evFork, cudaEventDisableTiming);
        cudaEventCreateWithFlags(&evJoin, cudaEventDisableTiming);
    }

    const int gemm_blocks = (NN + 127) / 128;
    const int gath_blocks = (NN * 32 + 255) / 256;   // warp per node

    // #1: layer-0 GEMM on side stream (overlaps CSR build)
    cudaEventRecord(evFork, 0);
    cudaStreamWaitEvent(s2, evFork, 0);
    k_gemm<IND><<<gemm_blocks, 256, 0, s2>>>(feats, W1, t_ptr);
    cudaEventRecord(evJoin, s2);

    // ---- CSR build: deg (int4), scan, fill
    k_deg<<<(EE / 4 + 255) / 256, 256>>>(dst);
    k_scan<<<SCB, 256>>>();
    k_fill<<<(EE + 255) / 256, 256>>>(src, dst);

    cudaStreamWaitEvent(0, evJoin, 0);

    // layer-0 gather
    k_gather<<<gath_blocks, 256>>>(t_ptr, h_ptr, b1, 0);

    // Hidden layers (relu)
    for (int l = 0; l < 2; l++) {
        k_gemm<HD><<<gemm_blocks, 256>>>(h_ptr, W2 + (size_t)l * HD * HD, t_ptr);
        k_gather<<<gath_blocks, 256>>>(t_ptr, h_ptr, b2 + (size_t)l * HD, 1);
    }

    // normalize + out_h + logits + log_softmax + fused loss
    k_normpred<<<NPB, 256>>>(h_ptr, out_h, W3, b3, out_pred, labels, tidx, out);
}